// round 10
// baseline (speedup 1.0000x reference)
#include <cuda_runtime.h>
#include <cuda_fp16.h>
#include <cstdint>

#define S_LEN 1024
#define CDIM 512
#define NH 8
#define DK 64
#define BDIM 4
// SCALE * log2(e) folded into Q at qkv epilogue
#define QSC 0.18033688011112042f

// fp16 scratch (static __device__ arrays per harness rules)
__device__ __half g_xh[BDIM * S_LEN * CDIM];        // x transposed: [b][i][c]
__device__ __half g_Wph[1536 * CDIM];
__device__ __half g_Woh[CDIM * CDIM];
__device__ __half g_Qh[BDIM * NH * S_LEN * DK];     // pre-scaled by QSC
__device__ __half g_Kh[BDIM * NH * S_LEN * DK];
__device__ __half g_Vh[BDIM * NH * S_LEN * DK];
__device__ __half g_resh[BDIM * S_LEN * CDIM];      // attn out: [b][i][h*64+d]

// ---------------------------------------------------------------------------
// helpers
// ---------------------------------------------------------------------------
__device__ __forceinline__ void mma_f16(float* d, const unsigned* a,
                                        const unsigned* b, const float* c) {
    asm volatile(
        "mma.sync.aligned.m16n8k16.row.col.f32.f16.f16.f32 "
        "{%0,%1,%2,%3},{%4,%5,%6,%7},{%8,%9},{%10,%11,%12,%13};"
        : "=f"(d[0]), "=f"(d[1]), "=f"(d[2]), "=f"(d[3])
        : "r"(a[0]), "r"(a[1]), "r"(a[2]), "r"(a[3]),
          "r"(b[0]), "r"(b[1]),
          "f"(c[0]), "f"(c[1]), "f"(c[2]), "f"(c[3]));
}
__device__ __forceinline__ void ldsm_x4(unsigned* r, uint32_t a) {
    asm volatile("ldmatrix.sync.aligned.m8n8.x4.shared.b16 {%0,%1,%2,%3}, [%4];"
                 : "=r"(r[0]), "=r"(r[1]), "=r"(r[2]), "=r"(r[3]) : "r"(a));
}
__device__ __forceinline__ void ldsm_x4_t(unsigned* r, uint32_t a) {
    asm volatile("ldmatrix.sync.aligned.m8n8.x4.trans.shared.b16 {%0,%1,%2,%3}, [%4];"
                 : "=r"(r[0]), "=r"(r[1]), "=r"(r[2]), "=r"(r[3]) : "r"(a));
}
__device__ __forceinline__ void cp16(unsigned dst, const void* src) {
    asm volatile("cp.async.cg.shared.global [%0], [%1], 16;" :: "r"(dst), "l"(src));
}
__device__ __forceinline__ void cp_commit() { asm volatile("cp.async.commit_group;"); }
template <int N> __device__ __forceinline__ void cp_wait() {
    asm volatile("cp.async.wait_group %0;" :: "n"(N));
}
__device__ __forceinline__ unsigned h2u(__half2 h) { return *(unsigned*)&h; }
__device__ __forceinline__ unsigned h2exp2(unsigned x) {
    unsigned r;
    asm("ex2.approx.f16x2 %0, %1;" : "=r"(r) : "r"(x));
    return r;
}

// ---------------------------------------------------------------------------
// Kernel 0: fused converts.
//   z < BDIM : transpose+convert x[b][c][i] f32 -> g_xh[b][i][c] fp16
//   z == BDIM: convert Wp (1536x512) + Wo (512x512) to fp16 (1M elems)
// ---------------------------------------------------------------------------
__global__ __launch_bounds__(256) void conv_kernel(const float* __restrict__ x,
                                                   const float* __restrict__ Wp,
                                                   const float* __restrict__ Wo) {
    if (blockIdx.z < BDIM) {
        __shared__ float t[32][33];
        int i0 = blockIdx.x * 32, c0 = blockIdx.y * 32, b = blockIdx.z;
        int tx = threadIdx.x & 31, ty = threadIdx.x >> 5;  // 32 x 8
        #pragma unroll
        for (int k = 0; k < 4; k++)
            t[ty + 8 * k][tx] = x[((size_t)b * CDIM + c0 + ty + 8 * k) * S_LEN + i0 + tx];
        __syncthreads();
        #pragma unroll
        for (int k = 0; k < 4; k++)
            g_xh[((size_t)b * S_LEN + i0 + ty + 8 * k) * CDIM + c0 + tx] =
                __float2half_rn(t[tx][ty + 8 * k]);
    } else {
        if (blockIdx.y >= 16) return;
        const size_t n1 = 1536 * CDIM;
        size_t flat = ((size_t)blockIdx.y * 32 + blockIdx.x) * 256 + threadIdx.x;
        size_t off = flat * 8;  // 8 halves per thread; groups never straddle n1
        const float* src; __half* dst; size_t o;
        if (off < n1) { src = Wp; dst = g_Wph; o = off; }
        else          { src = Wo; dst = g_Woh; o = off - n1; }
        float4 v0 = *(const float4*)&src[o];
        float4 v1 = *(const float4*)&src[o + 4];
        uint4 pk;
        pk.x = h2u(__floats2half2_rn(v0.x, v0.y));
        pk.y = h2u(__floats2half2_rn(v0.z, v0.w));
        pk.z = h2u(__floats2half2_rn(v1.x, v1.y));
        pk.w = h2u(__floats2half2_rn(v1.z, v1.w));
        *(uint4*)&dst[o] = pk;
    }
}

// ---------------------------------------------------------------------------
// Shared GEMM tile shape: block = 128 threads (4 warps), tile 128m x 64n,
// warp tile m32 x n64 (identical to R9's warp shape), K in chunks of 64
// halves (=128B swizzled rows), 2-stage cp.async pipeline.
// Stage layout: A[128 rows][128B] (16KB) + B[64 rows][128B] (8KB) = 24KB.
// ---------------------------------------------------------------------------
#define GSTG 24576

// ---------------------------------------------------------------------------
// Kernel 1: QKV projection.  A = g_xh[i][c], B = g_Wph[j][c].
// grid (i/128, j/64, b) = (8, 24, 4) = 768 CTAs.
// ---------------------------------------------------------------------------
__global__ __launch_bounds__(128, 4) void qkv_h(const float* __restrict__ bp) {
    extern __shared__ unsigned char smq[];
    int b  = blockIdx.z;
    int i0 = blockIdx.x * 128;
    int j0 = blockIdx.y * 64;
    int tid = threadIdx.x;
    int lane = tid & 31, warp = tid >> 5;
    int group = lane >> 2, tig = lane & 3;
    const __half* Ah = g_xh + ((size_t)b * S_LEN + i0) * CDIM;
    const __half* Bh = g_Wph + (size_t)j0 * CDIM;
    uint32_t sbase = (uint32_t)__cvta_generic_to_shared(smq);

    int b_row = tid >> 1, b_sb = (tid & 1) * 4;   // B: 64 rows, 2 thr/row

    float acc[2][8][4] = {};

    auto issue = [&](int t, int stg) {
        uint32_t Ab = sbase + (uint32_t)stg * GSTG, Bb = Ab + 16384u;
        #pragma unroll
        for (int seg = 0; seg < 8; seg++) {       // A: row = tid, all 8 chunks
            uint32_t soff = (uint32_t)(tid * 128) + (uint32_t)(((seg ^ (tid & 7)) << 4));
            cp16(Ab + soff, Ah + (size_t)tid * CDIM + t * 64 + seg * 8);
        }
        #pragma unroll
        for (int r = 0; r < 4; r++) {
            int seg = b_sb + r;
            uint32_t soff = (uint32_t)(b_row * 128) + (uint32_t)(((seg ^ (b_row & 7)) << 4));
            cp16(Bb + soff, Bh + (size_t)b_row * CDIM + t * 64 + seg * 8);
        }
        cp_commit();
    };

    issue(0, 0);
    issue(1, 1);

    int arow_lo = (lane & 7) + (((lane >> 3) & 1) << 3);
    int a_ch    = lane >> 4;
    int brow_lo = (lane & 7) + ((lane >> 4) << 3);
    int b_ch    = (lane >> 3) & 1;

    for (int t = 0; t < 8; ++t) {
        if (t == 7) cp_wait<0>(); else cp_wait<1>();
        __syncthreads();
        uint32_t Ab = sbase + (uint32_t)(t & 1) * GSTG, Bb = Ab + 16384u;

        #pragma unroll
        for (int kf = 0; kf < 4; kf++) {
            unsigned a[2][4], bf[8][2];
            #pragma unroll
            for (int mi = 0; mi < 2; mi++) {
                int row = warp * 32 + mi * 16 + arow_lo;
                int ch = 2 * kf + a_ch;
                ldsm_x4(a[mi], Ab + row * 128 + (((ch ^ (row & 7)) << 4)));
            }
            #pragma unroll
            for (int nf = 0; nf < 8; nf += 2) {
                int row = nf * 8 + brow_lo;
                int ch = 2 * kf + b_ch;
                unsigned r4[4];
                ldsm_x4(r4, Bb + row * 128 + (((ch ^ (row & 7)) << 4)));
                bf[nf][0] = r4[0]; bf[nf][1] = r4[1];
                bf[nf + 1][0] = r4[2]; bf[nf + 1][1] = r4[3];
            }
            #pragma unroll
            for (int mi = 0; mi < 2; mi++)
                #pragma unroll
                for (int nf = 0; nf < 8; nf++)
                    mma_f16(acc[mi][nf], a[mi], bf[nf], acc[mi][nf]);
        }
        __syncthreads();
        if (t + 2 < 8) issue(t + 2, t & 1);
    }

    // Epilogue: scatter fp16 into g_Qh/g_Kh/g_Vh, layout [b][h][i][d].
    // 64-wide j tiles align with the 192-wide head segments, so dst/sc are
    // uniform per (nf,tig) element pair.
    #pragma unroll
    for (int mi = 0; mi < 2; mi++) {
        int ir = i0 + warp * 32 + mi * 16 + group;
        #pragma unroll
        for (int nf = 0; nf < 8; nf++) {
            int j = j0 + nf * 8 + 2 * tig;
            int h = j / 192, rem = j - h * 192;
            __half* dst = (rem < DK) ? g_Qh : (rem < 2 * DK ? g_Kh : g_Vh);
            float sc = (rem < DK) ? QSC : 1.0f;
            int d = rem & 63;
            float b0 = bp[j], b1 = bp[j + 1];
            __half2 v01 = __floats2half2_rn((acc[mi][nf][0] + b0) * sc,
                                            (acc[mi][nf][1] + b1) * sc);
            __half2 v23 = __floats2half2_rn((acc[mi][nf][2] + b0) * sc,
                                            (acc[mi][nf][3] + b1) * sc);
            size_t base = (((size_t)b * NH + h) * S_LEN) * DK + d;
            *(__half2*)&dst[base + (size_t)ir * DK] = v01;
            *(__half2*)&dst[base + (size_t)(ir + 8) * DK] = v23;
        }
    }
}

// ---------------------------------------------------------------------------
// Kernel 2: flash attention (unchanged from R9).
// ---------------------------------------------------------------------------
#define ASTG 32768  // bytes per stage: K 16KB + V 16KB (128 keys)

__global__ __launch_bounds__(256, 2) void attn_h() {
    extern __shared__ unsigned char sma[];
    int bh = blockIdx.y;
    int i0 = blockIdx.x * 128;
    int tid = threadIdx.x;
    int lane = tid & 31, warp = tid >> 5;
    int group = lane >> 2, tig = lane & 3;
    const __half* Qp = g_Qh + (size_t)bh * S_LEN * DK;
    const __half* Kp = g_Kh + (size_t)bh * S_LEN * DK;
    const __half* Vp = g_Vh + (size_t)bh * S_LEN * DK;
    uint32_t sbase = (uint32_t)__cvta_generic_to_shared(sma);

    int l_row = tid >> 1;            // 128 key-rows, 2 threads/row
    int l_c0  = (tid & 1) * 4;       // 4 of 8 16B-chunks each

    auto issue = [&](int jt, int stg) {
        uint32_t Kb = sbase + (uint32_t)stg * ASTG, Vb = Kb + 16384u;
        #pragma unroll
        for (int cc = 0; cc < 4; cc++) {
            int c = l_c0 + cc;
            uint32_t soff = (uint32_t)(l_row * 128) + (uint32_t)(((c ^ (l_row & 7)) << 4));
            cp16(Kb + soff, Kp + (size_t)(jt + l_row) * DK + c * 8);
            cp16(Vb + soff, Vp + (size_t)(jt + l_row) * DK + c * 8);
        }
        cp_commit();
    };

    issue(0, 0);
    issue(128, 1);

    // Q fragments straight from global (already scaled by QSC)
    unsigned qa[4][4];
    int r0 = i0 + warp * 16 + group, r1 = r0 + 8;
    const unsigned* Qw = (const unsigned*)Qp;
    #pragma unroll
    for (int kf = 0; kf < 4; kf++) {
        qa[kf][0] = Qw[(size_t)r0 * 32 + kf * 8 + tig];
        qa[kf][1] = Qw[(size_t)r1 * 32 + kf * 8 + tig];
        qa[kf][2] = Qw[(size_t)r0 * 32 + kf * 8 + tig + 4];
        qa[kf][3] = Qw[(size_t)r1 * 32 + kf * 8 + tig + 4];
    }

    float o[8][4] = {};
    float oext[4] = {};                         // row-sum accumulator (ones column)
    const unsigned bones[2] = {0x3C003C00u, 0x3C003C00u};

    int brow_lo = (lane & 7) + ((lane >> 4) << 3);          // K rows
    int b_ch    = (lane >> 3) & 1;
    int vrow_lo = (lane & 7) + (((lane >> 3) & 1) << 3);    // V rows
    int v_ch    = lane >> 4;

    for (int t = 0; t < 8; ++t) {
        if (t == 7) cp_wait<0>(); else cp_wait<1>();
        __syncthreads();
        uint32_t Kb = sbase + (uint32_t)(t & 1) * ASTG, Vb = Kb + 16384u;

        #pragma unroll
        for (int hf = 0; hf < 2; hf++) {        // two 64-key chunks per stage
            uint32_t Kh = Kb + hf * 8192u, Vh = Vb + hf * 8192u;

            // S = Q K^T : m16 x n64(keys), k=64(d) in 4 k16 steps
            float s[8][4] = {};
            #pragma unroll
            for (int kf = 0; kf < 4; kf++) {
                unsigned bf[8][2];
                #pragma unroll
                for (int nf = 0; nf < 8; nf += 2) {
                    int row = nf * 8 + brow_lo;
                    int ch = 2 * kf + b_ch;
                    unsigned r4[4];
                    ldsm_x4(r4, Kh + row * 128 + (((ch ^ (row & 7)) << 4)));
                    bf[nf][0] = r4[0]; bf[nf][1] = r4[1];
                    bf[nf + 1][0] = r4[2]; bf[nf + 1][1] = r4[3];
                }
                #pragma unroll
                for (int nf = 0; nf < 8; nf++)
                    mma_f16(s[nf], qa[kf], bf[nf], s[nf]);
            }

            // P = 2^S in half2 (S already scaled); packs directly to A-frags
            unsigned ap[4][4];
            #pragma unroll
            for (int nf = 0; nf < 8; nf++) {
                unsigned hA = h2u(__floats2half2_rn(s[nf][0], s[nf][1]));
                unsigned hB = h2u(__floats2half2_rn(s[nf][2], s[nf][3]));
                int kf = nf >> 1, hi = (nf & 1) * 2;
                ap[kf][hi + 0] = h2exp2(hA);
                ap[kf][hi + 1] = h2exp2(hB);
            }

            // O += P V (and row-sums += P * ones)
            #pragma unroll
            for (int kf = 0; kf < 4; kf++) {
                unsigned bv[8][2];
                #pragma unroll
                for (int nf = 0; nf < 8; nf += 2) {
                    int row = kf * 16 + vrow_lo;
                    int ch = nf + v_ch;
                    unsigned r4[4];
                    ldsm_x4_t(r4, Vh + row * 128 + (((ch ^ (row & 7)) << 4)));
                    bv[nf][0] = r4[0]; bv[nf][1] = r4[1];
                    bv[nf + 1][0] = r4[2]; bv[nf + 1][1] = r4[3];
                }
                #pragma unroll
                for (int nf = 0; nf < 8; nf++)
                    mma_f16(o[nf], ap[kf], bv[nf], o[nf]);
                mma_f16(oext, ap[kf], bones, oext);
            }
        }
        __syncthreads();
        if (t + 2 < 8) issue((t + 2) * 128, t & 1);
    }

    // Denominators come straight from the ones-column accumulator.
    float inv0 = 1.f / oext[0], inv1 = 1.f / oext[2];

    // Epilogue -> g_resh[b][i][h*64+d] (fp16)
    int b = bh >> 3, h = bh & 7;
    #pragma unroll
    for (int nf = 0; nf < 8; nf++) {
        int d = h * DK + nf * 8 + 2 * tig;
        __half2 v0 = __floats2half2_rn(o[nf][0] * inv0, o[nf][1] * inv0);
        __half2 v1 = __floats2half2_rn(o[nf][2] * inv1, o[nf][3] * inv1);
        *(__half2*)&g_resh[((size_t)b * S_LEN + r0) * CDIM + d] = v0;
        *(__half2*)&g_resh[((size_t)b * S_LEN + r1) * CDIM + d] = v1;
    }
}

// ---------------------------------------------------------------------------
// Kernel 3: out[b,c,i] = sum_f res[b,i,f]*Wo[c,f] + bo[c] + x[b,c,i]
// A = g_Woh[c][f] (128 rows), B = g_resh[i][f] (64 rows).
// grid (i/64, c/128, b) = (16, 4, 4) = 256 CTAs of 128 threads.
// ---------------------------------------------------------------------------
__global__ __launch_bounds__(128, 4) void proj_h(const float* __restrict__ x,
                                                 const float* __restrict__ bo,
                                                 float* __restrict__ out) {
    extern __shared__ unsigned char smp[];
    int b  = blockIdx.z;
    int i0 = blockIdx.x * 64;
    int c0 = blockIdx.y * 128;
    int tid = threadIdx.x;
    int lane = tid & 31, warp = tid >> 5;
    int group = lane >> 2, tig = lane & 3;
    const __half* Ah = g_Woh + (size_t)c0 * CDIM;
    const __half* Bh = g_resh + ((size_t)b * S_LEN + i0) * CDIM;
    uint32_t sbase = (uint32_t)__cvta_generic_to_shared(smp);

    int b_row = tid >> 1, b_sb = (tid & 1) * 4;

    float acc[2][8][4] = {};

    auto issue = [&](int t, int stg) {
        uint32_t Ab = sbase + (uint32_t)stg * GSTG, Bb = Ab + 16384u;
        #pragma unroll
        for (int seg = 0; seg < 8; seg++) {
            uint32_t soff = (uint32_t)(tid * 128) + (uint32_t)(((seg ^ (tid & 7)) << 4));
            cp16(Ab + soff, Ah + (size_t)tid * CDIM + t * 64 + seg * 8);
        }
        #pragma unroll
        for (int r = 0; r < 4; r++) {
            int seg = b_sb + r;
            uint32_t soff = (uint32_t)(b_row * 128) + (uint32_t)(((seg ^ (b_row & 7)) << 4));
            cp16(Bb + soff, Bh + (size_t)b_row * CDIM + t * 64 + seg * 8);
        }
        cp_commit();
    };

    issue(0, 0);
    issue(1, 1);

    int arow_lo = (lane & 7) + (((lane >> 3) & 1) << 3);
    int a_ch    = lane >> 4;
    int brow_lo = (lane & 7) + ((lane >> 4) << 3);
    int b_ch    = (lane >> 3) & 1;

    for (int t = 0; t < 8; ++t) {
        if (t == 7) cp_wait<0>(); else cp_wait<1>();
        __syncthreads();
        uint32_t Ab = sbase + (uint32_t)(t & 1) * GSTG, Bb = Ab + 16384u;

        #pragma unroll
        for (int kf = 0; kf < 4; kf++) {
            unsigned a[2][4], bf[8][2];
            #pragma unroll
            for (int mi = 0; mi < 2; mi++) {
                int row = warp * 32 + mi * 16 + arow_lo;
                int ch = 2 * kf + a_ch;
                ldsm_x4(a[mi], Ab + row * 128 + (((ch ^ (row & 7)) << 4)));
            }
            #pragma unroll
            for (int nf = 0; nf < 8; nf += 2) {
                int row = nf * 8 + brow_lo;
                int ch = 2 * kf + b_ch;
                unsigned r4[4];
                ldsm_x4(r4, Bb + row * 128 + (((ch ^ (row & 7)) << 4)));
                bf[nf][0] = r4[0]; bf[nf][1] = r4[1];
                bf[nf + 1][0] = r4[2]; bf[nf + 1][1] = r4[3];
            }
            #pragma unroll
            for (int mi = 0; mi < 2; mi++)
                #pragma unroll
                for (int nf = 0; nf < 8; nf++)
                    mma_f16(acc[mi][nf], a[mi], bf[nf], acc[mi][nf]);
        }
        __syncthreads();
        if (t + 2 < 8) issue(t + 2, t & 1);
    }

    // Epilogue: bias + residual (f32), coalesced along i
    #pragma unroll
    for (int mi = 0; mi < 2; mi++) {
        int cr = c0 + warp * 32 + mi * 16 + group;
        #pragma unroll
        for (int nf = 0; nf < 8; nf++) {
            int ic = i0 + nf * 8 + 2 * tig;
            #pragma unroll
            for (int half = 0; half < 2; half++) {
                int c = cr + half * 8;
                size_t idx = ((size_t)b * CDIM + c) * S_LEN + ic;
                float2 xv = *(const float2*)&x[idx];
                float bias = bo[c];
                float2 ov;
                ov.x = acc[mi][nf][half * 2 + 0] + bias + xv.x;
                ov.y = acc[mi][nf][half * 2 + 1] + bias + xv.y;
                *(float2*)&out[idx] = ov;
            }
        }
    }
}

// ---------------------------------------------------------------------------
extern "C" void kernel_launch(void* const* d_in, const int* in_sizes, int n_in,
                              void* d_out, int out_size) {
    const float* x  = (const float*)d_in[0];
    const float* Wp = (const float*)d_in[1];
    const float* bp = (const float*)d_in[2];
    const float* Wo = (const float*)d_in[3];
    const float* bo = (const float*)d_in[4];
    float* out = (float*)d_out;

    const int gemm_smem = 2 * GSTG;   // 49152 B
    const int attn_smem = 2 * ASTG;   // 65536 B
    cudaFuncSetAttribute(qkv_h,  cudaFuncAttributeMaxDynamicSharedMemorySize, gemm_smem);
    cudaFuncSetAttribute(attn_h, cudaFuncAttributeMaxDynamicSharedMemorySize, attn_smem);
    cudaFuncSetAttribute(proj_h, cudaFuncAttributeMaxDynamicSharedMemorySize, gemm_smem);

    conv_kernel<<<dim3(32, 16, BDIM + 1), 256>>>(x, Wp, Wo);
    qkv_h<<<dim3(S_LEN / 128, 1536 / 64, BDIM), 128, gemm_smem>>>(bp);
    attn_h<<<dim3(S_LEN / 128, BDIM * NH), 256, attn_smem>>>();
    proj_h<<<dim3(S_LEN / 64, CDIM / 128, BDIM), 128, gemm_smem>>>(x, bo, out);
}

// round 12
// speedup vs baseline: 1.2752x; 1.2752x over previous
#include <cuda_runtime.h>
#include <cuda_fp16.h>
#include <cstdint>

#define S_LEN 1024
#define CDIM 512
#define NH 8
#define DK 64
#define BDIM 4
// SCALE * log2(e) folded into Q at qkv epilogue
#define QSC 0.18033688011112042f

// fp16 scratch (static __device__ arrays per harness rules)
__device__ __half g_xh[BDIM * S_LEN * CDIM];        // x transposed: [b][i][c]
__device__ __half g_Wph[1536 * CDIM];
__device__ __half g_Woh[CDIM * CDIM];
__device__ __half g_Qh[BDIM * NH * S_LEN * DK];     // pre-scaled by QSC
__device__ __half g_Kh[BDIM * NH * S_LEN * DK];
__device__ __half g_Vh[BDIM * NH * S_LEN * DK];
__device__ __half g_resh[BDIM * S_LEN * CDIM];      // attn out: [b][i][h*64+d]

// ---------------------------------------------------------------------------
// helpers
// ---------------------------------------------------------------------------
__device__ __forceinline__ void mma_f16(float* d, const unsigned* a,
                                        const unsigned* b, const float* c) {
    asm volatile(
        "mma.sync.aligned.m16n8k16.row.col.f32.f16.f16.f32 "
        "{%0,%1,%2,%3},{%4,%5,%6,%7},{%8,%9},{%10,%11,%12,%13};"
        : "=f"(d[0]), "=f"(d[1]), "=f"(d[2]), "=f"(d[3])
        : "r"(a[0]), "r"(a[1]), "r"(a[2]), "r"(a[3]),
          "r"(b[0]), "r"(b[1]),
          "f"(c[0]), "f"(c[1]), "f"(c[2]), "f"(c[3]));
}
__device__ __forceinline__ void ldsm_x4(unsigned* r, uint32_t a) {
    asm volatile("ldmatrix.sync.aligned.m8n8.x4.shared.b16 {%0,%1,%2,%3}, [%4];"
                 : "=r"(r[0]), "=r"(r[1]), "=r"(r[2]), "=r"(r[3]) : "r"(a));
}
__device__ __forceinline__ void ldsm_x4_t(unsigned* r, uint32_t a) {
    asm volatile("ldmatrix.sync.aligned.m8n8.x4.trans.shared.b16 {%0,%1,%2,%3}, [%4];"
                 : "=r"(r[0]), "=r"(r[1]), "=r"(r[2]), "=r"(r[3]) : "r"(a));
}
__device__ __forceinline__ void cp16(unsigned dst, const void* src) {
    asm volatile("cp.async.cg.shared.global [%0], [%1], 16;" :: "r"(dst), "l"(src));
}
__device__ __forceinline__ void cp_commit() { asm volatile("cp.async.commit_group;"); }
template <int N> __device__ __forceinline__ void cp_wait() {
    asm volatile("cp.async.wait_group %0;" :: "n"(N));
}
__device__ __forceinline__ unsigned h2u(__half2 h) { return *(unsigned*)&h; }
__device__ __forceinline__ unsigned h2exp2(unsigned x) {
    unsigned r;
    asm("ex2.approx.f16x2 %0, %1;" : "=r"(r) : "r"(x));
    return r;
}

// ---------------------------------------------------------------------------
// Kernel 0: fused converts.
//   z < BDIM : transpose+convert x[b][c][i] f32 -> g_xh[b][i][c] fp16
//   z == BDIM: convert Wp (1536x512) + Wo (512x512) to fp16 (1M elems)
// ---------------------------------------------------------------------------
__global__ __launch_bounds__(256) void conv_kernel(const float* __restrict__ x,
                                                   const float* __restrict__ Wp,
                                                   const float* __restrict__ Wo) {
    if (blockIdx.z < BDIM) {
        __shared__ float t[32][33];
        int i0 = blockIdx.x * 32, c0 = blockIdx.y * 32, b = blockIdx.z;
        int tx = threadIdx.x & 31, ty = threadIdx.x >> 5;  // 32 x 8
        #pragma unroll
        for (int k = 0; k < 4; k++)
            t[ty + 8 * k][tx] = x[((size_t)b * CDIM + c0 + ty + 8 * k) * S_LEN + i0 + tx];
        __syncthreads();
        #pragma unroll
        for (int k = 0; k < 4; k++)
            g_xh[((size_t)b * S_LEN + i0 + ty + 8 * k) * CDIM + c0 + tx] =
                __float2half_rn(t[tx][ty + 8 * k]);
    } else {
        if (blockIdx.y >= 16) return;
        const size_t n1 = 1536 * CDIM;
        size_t flat = ((size_t)blockIdx.y * 32 + blockIdx.x) * 256 + threadIdx.x;
        size_t off = flat * 8;  // 8 halves per thread; groups never straddle n1
        const float* src; __half* dst; size_t o;
        if (off < n1) { src = Wp; dst = g_Wph; o = off; }
        else          { src = Wo; dst = g_Woh; o = off - n1; }
        float4 v0 = *(const float4*)&src[o];
        float4 v1 = *(const float4*)&src[o + 4];
        uint4 pk;
        pk.x = h2u(__floats2half2_rn(v0.x, v0.y));
        pk.y = h2u(__floats2half2_rn(v0.z, v0.w));
        pk.z = h2u(__floats2half2_rn(v1.x, v1.y));
        pk.w = h2u(__floats2half2_rn(v1.z, v1.w));
        *(uint4*)&dst[o] = pk;
    }
}

// ---------------------------------------------------------------------------
// Kernel 1: QKV projection (fp16 mma).  A = g_xh[i][c], B = g_Wph[j][c].
// Tile 128m x 128n, K=512 in 8 chunks of 64 halves (128B swizzled rows).
// 3-stage cp.async pipeline, ONE barrier per tile.
// ---------------------------------------------------------------------------
#define GSTG 32768  // bytes per stage: A 16KB + B 16KB

__global__ __launch_bounds__(256, 2) void qkv_h(const float* __restrict__ bp) {
    extern __shared__ unsigned char smq[];
    int b  = blockIdx.z;
    int i0 = blockIdx.x * 128;
    int j0 = blockIdx.y * 128;
    int tid = threadIdx.x;
    int lane = tid & 31, warp = tid >> 5;
    int wm = warp >> 1, wn = warp & 1;
    int group = lane >> 2, tig = lane & 3;
    const __half* Ah = g_xh + ((size_t)b * S_LEN + i0) * CDIM;
    const __half* Bh = g_Wph + (size_t)j0 * CDIM;
    uint32_t sbase = (uint32_t)__cvta_generic_to_shared(smq);

    int l_row = tid >> 1;                 // 128 rows, 2 threads/row
    int l_sb  = (tid & 1) * 4;            // 4 of 8 16B-chunks each

    float acc[2][8][4] = {};

    auto issue = [&](int t, int stg) {
        uint32_t Ab = sbase + (uint32_t)stg * GSTG, Bb = Ab + 16384u;
        #pragma unroll
        for (int r = 0; r < 4; r++) {
            int seg = l_sb + r;
            uint32_t soff = (uint32_t)(l_row * 128) + (uint32_t)(((seg ^ (l_row & 7)) << 4));
            cp16(Ab + soff, Ah + (size_t)l_row * CDIM + t * 64 + seg * 8);
            cp16(Bb + soff, Bh + (size_t)l_row * CDIM + t * 64 + seg * 8);
        }
        cp_commit();
    };

    issue(0, 0);
    issue(1, 1);

    int arow_lo = (lane & 7) + (((lane >> 3) & 1) << 3);
    int a_ch    = lane >> 4;
    int brow_lo = (lane & 7) + ((lane >> 4) << 3);
    int b_ch    = (lane >> 3) & 1;

    for (int t = 0; t < 8; ++t) {
        if (t == 7) cp_wait<0>(); else cp_wait<1>();
        __syncthreads();
        if (t + 2 < 8) issue(t + 2, (t + 2) % 3);
        uint32_t Ab = sbase + (uint32_t)(t % 3) * GSTG, Bb = Ab + 16384u;

        #pragma unroll
        for (int kf = 0; kf < 4; kf++) {
            unsigned a[2][4], bf[8][2];
            #pragma unroll
            for (int mi = 0; mi < 2; mi++) {
                int row = wm * 32 + mi * 16 + arow_lo;
                int ch = 2 * kf + a_ch;
                ldsm_x4(a[mi], Ab + row * 128 + (((ch ^ (row & 7)) << 4)));
            }
            #pragma unroll
            for (int nf = 0; nf < 8; nf += 2) {
                int row = wn * 64 + nf * 8 + brow_lo;
                int ch = 2 * kf + b_ch;
                unsigned r4[4];
                ldsm_x4(r4, Bb + row * 128 + (((ch ^ (row & 7)) << 4)));
                bf[nf][0] = r4[0]; bf[nf][1] = r4[1];
                bf[nf + 1][0] = r4[2]; bf[nf + 1][1] = r4[3];
            }
            #pragma unroll
            for (int mi = 0; mi < 2; mi++)
                #pragma unroll
                for (int nf = 0; nf < 8; nf++)
                    mma_f16(acc[mi][nf], a[mi], bf[nf], acc[mi][nf]);
        }
    }

    // Epilogue: scatter fp16 into g_Qh/g_Kh/g_Vh, layout [b][h][i][d].
    // Q gets pre-scaled by QSC so attention needs no scaling before exp2.
    #pragma unroll
    for (int mi = 0; mi < 2; mi++) {
        int ir = i0 + wm * 32 + mi * 16 + group;
        #pragma unroll
        for (int nf = 0; nf < 8; nf++) {
            int j = j0 + wn * 64 + nf * 8 + 2 * tig;
            int h = j / 192, rem = j - h * 192;
            __half* dst = (rem < DK) ? g_Qh : (rem < 2 * DK ? g_Kh : g_Vh);
            float sc = (rem < DK) ? QSC : 1.0f;
            int d = rem & 63;
            float b0 = bp[j], b1 = bp[j + 1];
            __half2 v01 = __floats2half2_rn((acc[mi][nf][0] + b0) * sc,
                                            (acc[mi][nf][1] + b1) * sc);
            __half2 v23 = __floats2half2_rn((acc[mi][nf][2] + b0) * sc,
                                            (acc[mi][nf][3] + b1) * sc);
            size_t base = (((size_t)b * NH + h) * S_LEN) * DK + d;
            *(__half2*)&dst[base + (size_t)ir * DK] = v01;
            *(__half2*)&dst[base + (size_t)(ir + 8) * DK] = v23;
        }
    }
}

// ---------------------------------------------------------------------------
// Kernel 2: flash attention, fp16 mma, unstabilized softmax.
// 128-key stages, 3-stage cp.async pipeline, ONE barrier per stage,
// half2 ex2.approx softmax, tensor-core denominator (ones column).
// ---------------------------------------------------------------------------
#define ASTG 32768  // bytes per stage: K 16KB + V 16KB (128 keys)

__global__ __launch_bounds__(256, 2) void attn_h() {
    extern __shared__ unsigned char sma[];
    int bh = blockIdx.y;
    int i0 = blockIdx.x * 128;
    int tid = threadIdx.x;
    int lane = tid & 31, warp = tid >> 5;
    int group = lane >> 2, tig = lane & 3;
    const __half* Qp = g_Qh + (size_t)bh * S_LEN * DK;
    const __half* Kp = g_Kh + (size_t)bh * S_LEN * DK;
    const __half* Vp = g_Vh + (size_t)bh * S_LEN * DK;
    uint32_t sbase = (uint32_t)__cvta_generic_to_shared(sma);

    int l_row = tid >> 1;            // 128 key-rows, 2 threads/row
    int l_c0  = (tid & 1) * 4;       // 4 of 8 16B-chunks each

    auto issue = [&](int jt, int stg) {
        uint32_t Kb = sbase + (uint32_t)stg * ASTG, Vb = Kb + 16384u;
        #pragma unroll
        for (int cc = 0; cc < 4; cc++) {
            int c = l_c0 + cc;
            uint32_t soff = (uint32_t)(l_row * 128) + (uint32_t)(((c ^ (l_row & 7)) << 4));
            cp16(Kb + soff, Kp + (size_t)(jt + l_row) * DK + c * 8);
            cp16(Vb + soff, Vp + (size_t)(jt + l_row) * DK + c * 8);
        }
        cp_commit();
    };

    issue(0, 0);
    issue(128, 1);

    // Q fragments straight from global (already scaled by QSC)
    unsigned qa[4][4];
    int r0 = i0 + warp * 16 + group, r1 = r0 + 8;
    const unsigned* Qw = (const unsigned*)Qp;
    #pragma unroll
    for (int kf = 0; kf < 4; kf++) {
        qa[kf][0] = Qw[(size_t)r0 * 32 + kf * 8 + tig];
        qa[kf][1] = Qw[(size_t)r1 * 32 + kf * 8 + tig];
        qa[kf][2] = Qw[(size_t)r0 * 32 + kf * 8 + tig + 4];
        qa[kf][3] = Qw[(size_t)r1 * 32 + kf * 8 + tig + 4];
    }

    float o[8][4] = {};
    float oext[4] = {};                         // row-sum accumulator (ones column)
    const unsigned bones[2] = {0x3C003C00u, 0x3C003C00u};

    int brow_lo = (lane & 7) + ((lane >> 4) << 3);          // K rows
    int b_ch    = (lane >> 3) & 1;
    int vrow_lo = (lane & 7) + (((lane >> 3) & 1) << 3);    // V rows
    int v_ch    = lane >> 4;

    for (int t = 0; t < 8; ++t) {
        if (t == 7) cp_wait<0>(); else cp_wait<1>();
        __syncthreads();
        if (t + 2 < 8) issue((t + 2) * 128, (t + 2) % 3);
        uint32_t Kb = sbase + (uint32_t)(t % 3) * ASTG, Vb = Kb + 16384u;

        #pragma unroll
        for (int hf = 0; hf < 2; hf++) {        // two 64-key chunks per stage
            uint32_t Kh = Kb + hf * 8192u, Vh = Vb + hf * 8192u;

            // S = Q K^T : m16 x n64(keys), k=64(d) in 4 k16 steps
            float s[8][4] = {};
            #pragma unroll
            for (int kf = 0; kf < 4; kf++) {
                unsigned bf[8][2];
                #pragma unroll
                for (int nf = 0; nf < 8; nf += 2) {
                    int row = nf * 8 + brow_lo;
                    int ch = 2 * kf + b_ch;
                    unsigned r4[4];
                    ldsm_x4(r4, Kh + row * 128 + (((ch ^ (row & 7)) << 4)));
                    bf[nf][0] = r4[0]; bf[nf][1] = r4[1];
                    bf[nf + 1][0] = r4[2]; bf[nf + 1][1] = r4[3];
                }
                #pragma unroll
                for (int nf = 0; nf < 8; nf++)
                    mma_f16(s[nf], qa[kf], bf[nf], s[nf]);
            }

            // P = 2^S in half2 (S already scaled); packs directly to A-frags
            unsigned ap[4][4];
            #pragma unroll
            for (int nf = 0; nf < 8; nf++) {
                unsigned hA = h2u(__floats2half2_rn(s[nf][0], s[nf][1]));
                unsigned hB = h2u(__floats2half2_rn(s[nf][2], s[nf][3]));
                int kf = nf >> 1, hi = (nf & 1) * 2;
                ap[kf][hi + 0] = h2exp2(hA);
                ap[kf][hi + 1] = h2exp2(hB);
            }

            // O += P V (and row-sums += P * ones)
            #pragma unroll
            for (int kf = 0; kf < 4; kf++) {
                unsigned bv[8][2];
                #pragma unroll
                for (int nf = 0; nf < 8; nf += 2) {
                    int row = kf * 16 + vrow_lo;
                    int ch = nf + v_ch;
                    unsigned r4[4];
                    ldsm_x4_t(r4, Vh + row * 128 + (((ch ^ (row & 7)) << 4)));
                    bv[nf][0] = r4[0]; bv[nf][1] = r4[1];
                    bv[nf + 1][0] = r4[2]; bv[nf + 1][1] = r4[3];
                }
                #pragma unroll
                for (int nf = 0; nf < 8; nf++)
                    mma_f16(o[nf], ap[kf], bv[nf], o[nf]);
                mma_f16(oext, ap[kf], bones, oext);
            }
        }
    }

    // Denominators come straight from the ones-column accumulator.
    float inv0 = 1.f / oext[0], inv1 = 1.f / oext[2];

    // Epilogue -> g_resh[b][i][h*64+d] (fp16)
    int b = bh >> 3, h = bh & 7;
    #pragma unroll
    for (int nf = 0; nf < 8; nf++) {
        int d = h * DK + nf * 8 + 2 * tig;
        __half2 v0 = __floats2half2_rn(o[nf][0] * inv0, o[nf][1] * inv0);
        __half2 v1 = __floats2half2_rn(o[nf][2] * inv1, o[nf][3] * inv1);
        *(__half2*)&g_resh[((size_t)b * S_LEN + r0) * CDIM + d] = v0;
        *(__half2*)&g_resh[((size_t)b * S_LEN + r1) * CDIM + d] = v1;
    }
}

// ---------------------------------------------------------------------------
// Kernel 3: out[b,c,i] = sum_f res[b,i,f]*Wo[c,f] + bo[c] + x[b,c,i]
// A = g_Woh[c][f], B = g_resh[i][f]. fp16 mma, 3-stage single-barrier core.
// ---------------------------------------------------------------------------
__global__ __launch_bounds__(256, 2) void proj_h(const float* __restrict__ x,
                                                 const float* __restrict__ bo,
                                                 float* __restrict__ out) {
    extern __shared__ unsigned char smp[];
    int b  = blockIdx.z;
    int i0 = blockIdx.x * 128;
    int c0 = blockIdx.y * 128;
    int tid = threadIdx.x;
    int lane = tid & 31, warp = tid >> 5;
    int wm = warp >> 1, wn = warp & 1;
    int group = lane >> 2, tig = lane & 3;
    const __half* Ah = g_Woh + (size_t)c0 * CDIM;
    const __half* Bh = g_resh + ((size_t)b * S_LEN + i0) * CDIM;
    uint32_t sbase = (uint32_t)__cvta_generic_to_shared(smp);

    int l_row = tid >> 1;
    int l_sb  = (tid & 1) * 4;

    float acc[2][8][4] = {};

    auto issue = [&](int t, int stg) {
        uint32_t Ab = sbase + (uint32_t)stg * GSTG, Bb = Ab + 16384u;
        #pragma unroll
        for (int r = 0; r < 4; r++) {
            int seg = l_sb + r;
            uint32_t soff = (uint32_t)(l_row * 128) + (uint32_t)(((seg ^ (l_row & 7)) << 4));
            cp16(Ab + soff, Ah + (size_t)l_row * CDIM + t * 64 + seg * 8);
            cp16(Bb + soff, Bh + (size_t)l_row * CDIM + t * 64 + seg * 8);
        }
        cp_commit();
    };

    issue(0, 0);
    issue(1, 1);

    int arow_lo = (lane & 7) + (((lane >> 3) & 1) << 3);
    int a_ch    = lane >> 4;
    int brow_lo = (lane & 7) + ((lane >> 4) << 3);
    int b_ch    = (lane >> 3) & 1;

    for (int t = 0; t < 8; ++t) {
        if (t == 7) cp_wait<0>(); else cp_wait<1>();
        __syncthreads();
        if (t + 2 < 8) issue(t + 2, (t + 2) % 3);
        uint32_t Ab = sbase + (uint32_t)(t % 3) * GSTG, Bb = Ab + 16384u;

        #pragma unroll
        for (int kf = 0; kf < 4; kf++) {
            unsigned a[2][4], bf[8][2];
            #pragma unroll
            for (int mi = 0; mi < 2; mi++) {
                int row = wm * 32 + mi * 16 + arow_lo;
                int ch = 2 * kf + a_ch;
                ldsm_x4(a[mi], Ab + row * 128 + (((ch ^ (row & 7)) << 4)));
            }
            #pragma unroll
            for (int nf = 0; nf < 8; nf += 2) {
                int row = wn * 64 + nf * 8 + brow_lo;
                int ch = 2 * kf + b_ch;
                unsigned r4[4];
                ldsm_x4(r4, Bb + row * 128 + (((ch ^ (row & 7)) << 4)));
                bf[nf][0] = r4[0]; bf[nf][1] = r4[1];
                bf[nf + 1][0] = r4[2]; bf[nf + 1][1] = r4[3];
            }
            #pragma unroll
            for (int mi = 0; mi < 2; mi++)
                #pragma unroll
                for (int nf = 0; nf < 8; nf++)
                    mma_f16(acc[mi][nf], a[mi], bf[nf], acc[mi][nf]);
        }
    }

    // Epilogue: bias + residual (f32), coalesced along i
    #pragma unroll
    for (int mi = 0; mi < 2; mi++) {
        int cr = c0 + wm * 32 + mi * 16 + group;
        #pragma unroll
        for (int nf = 0; nf < 8; nf++) {
            int ic = i0 + wn * 64 + nf * 8 + 2 * tig;
            #pragma unroll
            for (int half = 0; half < 2; half++) {
                int c = cr + half * 8;
                size_t idx = ((size_t)b * CDIM + c) * S_LEN + ic;
                float2 xv = *(const float2*)&x[idx];
                float bias = bo[c];
                float2 ov;
                ov.x = acc[mi][nf][half * 2 + 0] + bias + xv.x;
                ov.y = acc[mi][nf][half * 2 + 1] + bias + xv.y;
                *(float2*)&out[idx] = ov;
            }
        }
    }
}

// ---------------------------------------------------------------------------
extern "C" void kernel_launch(void* const* d_in, const int* in_sizes, int n_in,
                              void* d_out, int out_size) {
    const float* x  = (const float*)d_in[0];
    const float* Wp = (const float*)d_in[1];
    const float* bp = (const float*)d_in[2];
    const float* Wo = (const float*)d_in[3];
    const float* bo = (const float*)d_in[4];
    float* out = (float*)d_out;

    const int gemm_smem = 3 * GSTG;   // 98304 B
    const int attn_smem = 3 * ASTG;   // 98304 B
    cudaFuncSetAttribute(qkv_h,  cudaFuncAttributeMaxDynamicSharedMemorySize, gemm_smem);
    cudaFuncSetAttribute(attn_h, cudaFuncAttributeMaxDynamicSharedMemorySize, attn_smem);
    cudaFuncSetAttribute(proj_h, cudaFuncAttributeMaxDynamicSharedMemorySize, gemm_smem);

    conv_kernel<<<dim3(32, 16, BDIM + 1), 256>>>(x, Wp, Wo);
    qkv_h<<<dim3(S_LEN / 128, 1536 / 128, BDIM), 256, gemm_smem>>>(bp);
    attn_h<<<dim3(S_LEN / 128, BDIM * NH), 256, attn_smem>>>();
    proj_h<<<dim3(S_LEN / 128, CDIM / 128, BDIM), 256, gemm_smem>>>(x, bo, out);
}